// round 15
// baseline (speedup 1.0000x reference)
#include <cuda_runtime.h>
#include <math.h>

#define NI   128
#define ND   32
#define NH   4
#define NNEI 120
#define HC   (NH * NI)   // 512
#define BLOC 14
#define NTHR 512
#define SLABF (NNEI * NI)   // 15360 floats, XOR-swizzled, stride 128

// ---------------- scratch (device globals) ----------------
__device__ float g_Mq[NI * HC];       // 128 x 512 : combined q/k projection (incl 1/sqrt(32))
__device__ float g_W2[HC * NI];       // 512 x 128 : combined v-projection @ Wh

// ---------------- K0: precompute Mq and W2 ----------------
__global__ void weights_prep_kernel(const float* __restrict__ Wq,
                                    const float* __restrict__ Wkv,
                                    const float* __restrict__ Wh)
{
    const int gid = blockIdx.x * blockDim.x + threadIdx.x;
    if (gid < NI * HC) {
        const int e = gid >> 9;
        const int hc = gid & 511;
        const int h = hc >> 7;
        const int c = hc & 127;
        float s = 0.f;
#pragma unroll
        for (int d = 0; d < ND; d++)
            s += Wq[e * 128 + d * 4 + h] * Wkv[c * 640 + d * 4 + h];
        g_Mq[gid] = s * 0.17677669529663687f;   // 1/sqrt(32)
    } else {
        const int g = gid - NI * HC;
        const int r = g >> 7;          // h*128 + c
        const int i = g & 127;
        const int h = r >> 7;
        const int c = r & 127;
        float s = 0.f;
#pragma unroll 8
        for (int ip = 0; ip < 128; ip++)
            s += Wkv[c * 640 + (32 + ip) * 4 + h] * Wh[(h * 128 + ip) * 128 + i];
        g_W2[g] = s;
    }
}

// ---------------- smem float layout (all 16B-aligned) ----------------
#define SO_SLAB0  0                        // 15360  stream-0 slab
#define SO_SLAB1  15360                    // 15360  stream-1 slab
#define SO_QW     30720                    // 7168 = 14*512 qw[il][h*128+c] (epi partials reuse)
#define SO_ACC    37888                    // 8192 = 512*16 accT[hc][l] stride16 (g1s overlaid)
#define SO_PARTL0 46080                    // 2048 (mask staging overlaid in prologue)
#define SO_PARTW0 48128                    // 1024
#define SO_WT0    49152                    // 512
#define SO_PARTL1 49664                    // 2048
#define SO_PARTW1 51712                    // 1024
#define SO_WT1    52736                    // 512
#define SO_SW     53248                    // 1696
#define SO_MSK    54944                    // 1696 ints
#define SO_FLAG   56640                    // flags
#define SMEM_FLOATS (SO_FLAG + 8)
#define SMEM_BYTES  (SMEM_FLOATS * 4)      // 226,592 B -> 1 CTA/SM

__device__ __forceinline__ void cpa16(void* dst, const void* src)
{
    unsigned s = (unsigned)__cvta_generic_to_shared(dst);
    asm volatile("cp.async.cg.shared.global [%0], [%1], 16;\n" :: "r"(s), "l"(src));
}
__device__ __forceinline__ void cpa8(void* dst, const void* src)
{
    unsigned s = (unsigned)__cvta_generic_to_shared(dst);
    asm volatile("cp.async.ca.shared.global [%0], [%1], 8;\n" :: "r"(s), "l"(src));
}
__device__ __forceinline__ void cpa_commit()
{
    asm volatile("cp.async.commit_group;\n" ::: "memory");
}

// 256-thread slab stage into XOR-swizzled layout; one commit group. t in [0,256).
__device__ __forceinline__ void stage_slab_256(float* dst, const float* gsrc, int t)
{
#pragma unroll
    for (int w = 0; w < 15; w++) {
        const int idx = t + w * 256;          // 15*256 == 3840 == SLABF/4 exactly
        const int j = idx >> 5, q = idx & 31;
        cpa16(dst + j * NI + ((q ^ (j & 7)) << 2), gsrc + idx * 4);
    }
    cpa_commit();
}

__global__ __launch_bounds__(NTHR, 1) void attn_2stream(
    const float* __restrict__ g1,
    const float* __restrict__ gg1,
    const void*  __restrict__ maskRaw,
    const float* __restrict__ sw,
    const float* __restrict__ bh,
    float* __restrict__ out,
    int nloctot)
{
    extern __shared__ float sm[];
    float* qw     = sm + SO_QW;
    float* accT   = sm + SO_ACC;
    float* g1s    = accT;                   // prologue overlay [0..1792)
    int*   mstage = (int*)(sm + SO_PARTL0); // prologue overlay (<=1680 ints)
    float* sws    = sm + SO_SW;
    int*   msks   = (int*)(sm + SO_MSK);
    int*   flags  = (int*)(sm + SO_FLAG);

    const int tid = threadIdx.x;
    const int locbase = blockIdx.x * BLOC;
    const int count = min(BLOC, nloctot - locbase);
    if (count <= 0) return;

    const int strm = tid >> 8;              // stream id 0/1
    const int ts = tid & 255;               // thread id within stream

    if (tid == 0) { flags[0] = 0; flags[1] = 0; }

    // each stream prefetches its OWN first slab (stream s -> loc s)
    if (strm < count)
        stage_slab_256(sm + (strm ? SO_SLAB1 : SO_SLAB0),
                       gg1 + (size_t)(locbase + strm) * SLABF, ts);

    // mask dtype detection from first 1KB (deterministic)
    if (tid < 64) {
        const uint4 v = ((const uint4*)maskRaw)[tid];
        const unsigned orw = v.x | v.y | v.z | v.w;
        if (orw & 0x00FFFF00u) atomicOr(&flags[0], 1);
        if (orw & 0xFF000000u) atomicOr(&flags[1], 1);
    }
    // g1 rows (overlaid on accT)
    if (tid < 32 * BLOC) {
        const int l = tid >> 5, e4 = tid & 31;
        if (l < count)
            *(float4*)&g1s[l * NI + e4 * 4] =
                *(const float4*)&g1[(size_t)(locbase + l) * NI + e4 * 4];
    }
    __syncthreads();   // B0

    const int f12 = flags[0], f3 = flags[1];
    const int nel = count * NNEI;

    // stage sw + raw mask via cp.async — overlaps qw projection
    {
        const float* swsrc = sw + (size_t)locbase * NNEI;
        for (int t2 = tid; t2 < (nel >> 2); t2 += NTHR)
            cpa16(sws + t2 * 4, swsrc + t2 * 4);
        if (f12) {
            const char* mb = (const char*)maskRaw + (size_t)locbase * NNEI;
            for (int t2 = tid; t2 < (nel >> 3); t2 += NTHR)
                cpa8((char*)mstage + t2 * 8, mb + t2 * 8);
        } else {
            const char* mb = (const char*)maskRaw + (size_t)locbase * NNEI * 4;
            for (int t2 = tid; t2 < (nel >> 2); t2 += NTHR)
                cpa16((char*)mstage + t2 * 16, mb + t2 * 16);
        }
        cpa_commit();
    }

    // qw projection (R7 scalar): qw[l][n] = g1[l,:] . Mq[:,n], n = tid
    {
        float acc[BLOC];
#pragma unroll
        for (int l = 0; l < BLOC; l++) acc[l] = 0.f;
        const float* mq = g_Mq + tid;
#pragma unroll 8
        for (int e = 0; e < NI; e++) {
            const float m = mq[e * HC];
#pragma unroll
            for (int l = 0; l < BLOC; l++)
                acc[l] += g1s[l * NI + e] * m;
        }
        __syncthreads();   // B1: g1s reads done (accT free)
#pragma unroll
        for (int l = 0; l < BLOC; l++) qw[l * HC + tid] = acc[l];
    }

    // drain ALL prologue groups (slabs + staging); convert mask
    asm volatile("cp.async.wait_group 0;\n" ::: "memory");
    __syncthreads();       // B2
#pragma unroll
    for (int w = 0; w < 4; w++) {
        const int t2 = tid + w * NTHR;
        if (t2 < nel) {
            int m;
            if (f12)      m = ((const unsigned char*)mstage)[t2] != 0;
            else if (f3)  m = ((const float*)mstage)[t2] != 0.f;
            else          m = mstage[t2] != 0;
            msks[t2] = m;
        }
    }
    __syncthreads();       // B3: msks ready; partL0 (mstage) free

    // ---------------- per-stream resources & mappings ----------------
    float* slab  = sm + (strm ? SO_SLAB1  : SO_SLAB0);
    float* partL = sm + (strm ? SO_PARTL1 : SO_PARTL0);
    float* partW = sm + (strm ? SO_PARTW1 : SO_PARTW0);
    float* wt    = sm + (strm ? SO_WT1    : SO_WT0);
    const int barid = 1 + strm;             // named barrier per stream (0 = __syncthreads)

    const int lane = tid & 31;
    const int wid2 = ts >> 5;
    const int kq2 = wid2 & 3;                    // logits k-quarter
    const int jb = ((wid2 >> 2) << 5) + lane;    // logits row base in [0,64)
    const int cw = ts & 127, gh = ts >> 7;       // wsum column / row-group
    const int c4 = cw >> 2, co = cw & 3;

    // ---------------- independent per-stream loop (locs strm, strm+2, ...) ----------------
    for (int il = strm; il < count; il += 2) {
        // slab il requested by THIS stream's threads (prologue or prev iter).
        // Drain own copies, then publish across the stream's 256 threads.
        asm volatile("cp.async.wait_group 0;\n" ::: "memory");
        asm volatile("bar.sync %0, 256;" :: "r"(barid) : "memory");

        // --- logits(il): rows jb and jb+64, 4 heads each ---
        {
            const float* qwl = qw + il * HC;
            const int jA = jb;
            const int jB = jb + 64;
            const int doB = (jB < NNEI);
            const float* grA = slab + jA * NI + kq2 * 32;
            const float* grB = slab + jB * NI + kq2 * 32;
            const int jmA = jA & 7;
            const int jmB = jB & 7;
            const float4* q0 = (const float4*)(qwl + 0 * NI + kq2 * 32);
            const float4* q1 = (const float4*)(qwl + 1 * NI + kq2 * 32);
            const float4* q2 = (const float4*)(qwl + 2 * NI + kq2 * 32);
            const float4* q3 = (const float4*)(qwl + 3 * NI + kq2 * 32);
            float p0 = 0.f, p1 = 0.f, p2 = 0.f, p3 = 0.f;
            float r0 = 0.f, r1 = 0.f, r2 = 0.f, r3 = 0.f;
#pragma unroll
            for (int i = 0; i < 8; i++) {
                const float4 a = q0[i];
                const float4 b = q1[i];
                const float4 c = q2[i];
                const float4 d = q3[i];
                const float4 gA = *(const float4*)(grA + ((i ^ jmA) << 2));
                p0 += gA.x*a.x + gA.y*a.y + gA.z*a.z + gA.w*a.w;
                p1 += gA.x*b.x + gA.y*b.y + gA.z*b.z + gA.w*b.w;
                p2 += gA.x*c.x + gA.y*c.y + gA.z*c.z + gA.w*c.w;
                p3 += gA.x*d.x + gA.y*d.y + gA.z*d.z + gA.w*d.w;
                if (doB) {
                    const float4 gB = *(const float4*)(grB + ((i ^ jmB) << 2));
                    r0 += gB.x*a.x + gB.y*a.y + gB.z*a.z + gB.w*a.w;
                    r1 += gB.x*b.x + gB.y*b.y + gB.z*b.z + gB.w*b.w;
                    r2 += gB.x*c.x + gB.y*c.y + gB.z*c.z + gB.w*c.w;
                    r3 += gB.x*d.x + gB.y*d.y + gB.z*d.z + gB.w*d.w;
                }
            }
            partL[kq2 * HC + 0 * NI + jA] = p0;
            partL[kq2 * HC + 1 * NI + jA] = p1;
            partL[kq2 * HC + 2 * NI + jA] = p2;
            partL[kq2 * HC + 3 * NI + jA] = p3;
            if (doB) {
                partL[kq2 * HC + 0 * NI + jB] = r0;
                partL[kq2 * HC + 1 * NI + jB] = r1;
                partL[kq2 * HC + 2 * NI + jB] = r2;
                partL[kq2 * HC + 3 * NI + jB] = r3;
            }
        }
        asm volatile("bar.sync %0, 256;" :: "r"(barid) : "memory");

        // --- masked softmax * sw (stream's warps 0-3; one warp per head) ---
        if (ts < 128) {
            const int h = ts >> 5, ln = ts & 31;
            float lv[4]; int mk[4];
            float mx = -INFINITY;
#pragma unroll
            for (int q = 0; q < 4; q++) {
                const int j = ln + q * 32;
                const int in = (j < NNEI) ? msks[il * NNEI + j] : 0;
                float L = -INFINITY;
                if (in) L = partL[h * NI + j] + partL[HC + h * NI + j]
                          + partL[2 * HC + h * NI + j] + partL[3 * HC + h * NI + j];
                lv[q] = L; mk[q] = in;
                mx = fmaxf(mx, L);
            }
#pragma unroll
            for (int off = 16; off > 0; off >>= 1)
                mx = fmaxf(mx, __shfl_xor_sync(0xFFFFFFFFu, mx, off));
            float ev[4];
            float sum = 0.f;
#pragma unroll
            for (int q = 0; q < 4; q++) {
                ev[q] = mk[q] ? __expf(lv[q] - mx) : 0.f;
                sum += ev[q];
            }
#pragma unroll
            for (int off = 16; off > 0; off >>= 1)
                sum += __shfl_xor_sync(0xFFFFFFFFu, sum, off);
            const float inv = (sum > 0.f) ? (1.f / sum) : 0.f;
#pragma unroll
            for (int q = 0; q < 4; q++) {
                const int j = ln + q * 32;
                if (j < NNEI)
                    wt[j * 4 + h] = mk[q] ? ev[q] * inv * sws[il * NNEI + j] : 0.f;
            }
        }
        asm volatile("bar.sync %0, 256;" :: "r"(barid) : "memory");

        // --- wsum(il): row-group gh owns rows [60*gh, 60*gh+60) ---
        {
            float s0 = 0.f, s1 = 0.f, s2 = 0.f, s3 = 0.f;
            const int j0 = gh * 60;
#pragma unroll 15
            for (int t = 0; t < 60; t++) {
                const int j = j0 + t;
                const float g = slab[j * NI + (((c4 ^ (j & 7)) << 2) | co)];
                const float4 w = *(const float4*)&wt[j * 4];
                s0 += w.x * g; s1 += w.y * g; s2 += w.z * g; s3 += w.w * g;
            }
            partW[gh * HC + 0 * NI + cw] = s0;
            partW[gh * HC + 1 * NI + cw] = s1;
            partW[gh * HC + 2 * NI + cw] = s2;
            partW[gh * HC + 3 * NI + cw] = s3;
        }
        asm volatile("bar.sync %0, 256;" :: "r"(barid) : "memory");
        // slab il free; partW fully visible

        // accT column il (2 values per thread)
        accT[(ts << 4) + il]         = partW[ts]       + partW[HC + ts];
        accT[((ts + 256) << 4) + il] = partW[ts + 256] + partW[HC + ts + 256];

        // prefetch this stream's next slab (il+2) into its freed buffer
        if (il + 2 < count)
            stage_slab_256(slab, gg1 + (size_t)(locbase + il + 2) * SLABF, ts);
    }
    __syncthreads();   // both streams done; accT complete

    // ---------------- fused output GEMM (R7 scalar): out[l][128] = a[l][512] @ W2 + bh ----------------
    {
        const int i = tid & 127, h2 = tid >> 7;
        float acc[BLOC];
#pragma unroll
        for (int l = 0; l < BLOC; l++) acc[l] = 0.f;
        const float* w2p = g_W2 + (size_t)(h2 * NI) * NI + i;
#pragma unroll 4
        for (int k = 0; k < 128; k++) {
            const float w2 = w2p[k * NI];
            const float* ap = accT + ((h2 * 128 + k) << 4);
            const float4 v0 = *(const float4*)ap;
            const float4 v1 = *(const float4*)(ap + 4);
            const float4 v2 = *(const float4*)(ap + 8);
            const float2 v3 = *(const float2*)(ap + 12);
            acc[0]  += v0.x * w2; acc[1]  += v0.y * w2;
            acc[2]  += v0.z * w2; acc[3]  += v0.w * w2;
            acc[4]  += v1.x * w2; acc[5]  += v1.y * w2;
            acc[6]  += v1.z * w2; acc[7]  += v1.w * w2;
            acc[8]  += v2.x * w2; acc[9]  += v2.y * w2;
            acc[10] += v2.z * w2; acc[11] += v2.w * w2;
            acc[12] += v3.x * w2; acc[13] += v3.y * w2;
        }
        __syncthreads();
#pragma unroll
        for (int l = 0; l < BLOC; l++)
            qw[h2 * (BLOC * NI) + l * NI + i] = acc[l];   // reuse qw as partials
    }
    __syncthreads();
    for (int o = tid; o < BLOC * NI; o += NTHR) {
        const int l = o >> 7, ii = o & 127;
        if (l < count) {
            const float v = qw[o] + qw[BLOC * NI + o]
                          + qw[2 * BLOC * NI + o] + qw[3 * BLOC * NI + o] + bh[ii];
            out[(size_t)(locbase + l) * NI + ii] = v;
        }
    }
}

// ---------------- launch ----------------
extern "C" void kernel_launch(void* const* d_in, const int* in_sizes, int n_in,
                              void* d_out, int out_size)
{
    const float* g1   = (const float*)d_in[0];
    const float* gg1  = (const float*)d_in[1];
    const void*  mask = d_in[2];
    const float* sw   = (const float*)d_in[3];
    const float* Wq   = (const float*)d_in[4];
    const float* Wkv  = (const float*)d_in[5];
    const float* Wh   = (const float*)d_in[6];
    const float* bh   = (const float*)d_in[7];
    float* out = (float*)d_out;

    const int nloctot = in_sizes[0] / NI;   // 2048

    static int smem_cfg = 0;
    if (!smem_cfg) {
        cudaFuncSetAttribute(attn_2stream, cudaFuncAttributeMaxDynamicSharedMemorySize, SMEM_BYTES);
        smem_cfg = 1;
    }

    const int grid = (nloctot + BLOC - 1) / BLOC;   // 147

    weights_prep_kernel<<<512, 256>>>(Wq, Wkv, Wh);
    attn_2stream<<<grid, NTHR, SMEM_BYTES>>>(g1, gg1, mask, sw, bh, out, nloctot);
}

// round 17
// speedup vs baseline: 1.1646x; 1.1646x over previous
#include <cuda_runtime.h>
#include <math.h>

#define NI   128
#define ND   32
#define NH   4
#define NNEI 120
#define HC   (NH * NI)   // 512
#define BLOC 14
#define NTHR 512
#define SLABF (NNEI * NI)   // 15360 floats, XOR-swizzled, stride 128

// ---------------- scratch (device globals) ----------------
__device__ float g_Mq[NI * HC];       // 128 x 512 : combined q/k projection (incl 1/sqrt(32))
__device__ float g_W2[HC * NI];       // 512 x 128 : combined v-projection @ Wh

// ---------------- K0 (tiled smem mini-GEMMs) ----------------
// blocks 0..15  : Mq  (h = b>>2, e-tile = (b&3)*32)
// blocks 16..79 : W2  (b2 = b-16: h = b2>>4, c-tile = (b2&15)*8)
__global__ __launch_bounds__(256) void wprep_tiled(const float* __restrict__ Wq,
                                                   const float* __restrict__ Wkv,
                                                   const float* __restrict__ Wh)
{
    __shared__ float smbuf[5280];
    const int tid = threadIdx.x;
    const int b = blockIdx.x;

    if (b < 16) {
        // ---- Mq[e, h*128+c] = (1/sqrt(32)) * sum_d Wq[e,4d+h] * Wkv[c*640+4d+h]
        const int h = b >> 2;
        const int e0 = (b & 3) * 32;
        float* As = smbuf;            // [32][33]  e-tile x d
        float* Bs = smbuf + 1056;     // [128][33] c x d

        // stage A (1024 elems): lanes vary d -> 4-line gather
#pragma unroll
        for (int k = 0; k < 4; k++) {
            const int idx = tid + k * 256;
            const int el = idx >> 5, d = idx & 31;
            As[el * 33 + d] = Wq[(e0 + el) * 128 + 4 * d + h];
        }
        // stage B (4096 elems)
#pragma unroll
        for (int k = 0; k < 16; k++) {
            const int idx = tid + k * 256;
            const int c = idx >> 5, d = idx & 31;
            Bs[c * 33 + d] = Wkv[c * 640 + 4 * d + h];
        }
        __syncthreads();

        // compute: c = tid&127 ; 16 e-rows per thread
        const int c = tid & 127;
        const int eo = (tid >> 7) * 16;
        const float* brow = Bs + c * 33;
#pragma unroll
        for (int e2 = 0; e2 < 16; e2++) {
            const int el = eo + e2;
            const float* arow = As + el * 33;
            float s = 0.f;
#pragma unroll
            for (int d = 0; d < 32; d++)
                s += arow[d] * brow[d];
            g_Mq[(e0 + el) * HC + h * 128 + c] = s * 0.17677669529663687f;
        }
    } else {
        // ---- W2[h*128+c, i] = sum_ip Wkv[c*640+(32+ip)*4+h] * Wh[(h*128+ip)*128+i]
        const int b2 = b - 16;
        const int h = b2 >> 4;
        const int c0 = (b2 & 15) * 8;
        float* Wks = smbuf;           // [8][129]  c x ip
        float* Whs = smbuf + 1032;    // [32][128] ip-chunk x i

        // stage Wks (1024 elems): lanes vary ip -> 4-line gather
#pragma unroll
        for (int k = 0; k < 4; k++) {
            const int idx = tid + k * 256;
            const int cl2 = idx >> 7, ip = idx & 127;
            Wks[cl2 * 129 + ip] = Wkv[(c0 + cl2) * 640 + (32 + ip) * 4 + h];
        }

        const int i4 = tid & 31;          // float4 column group
        const int cl = tid >> 5;          // c within tile (8 groups)
        const float* wksrow = Wks + cl * 129;
        float4 acc = make_float4(0.f, 0.f, 0.f, 0.f);

        for (int q = 0; q < 4; q++) {
            const int ip0 = q * 32;
            __syncthreads();   // prev Whs chunk consumed / Wks staged
            // stage Wh chunk [32 x 128] coalesced float4
#pragma unroll
            for (int k = 0; k < 4; k++) {
                const int idx = tid + k * 256;   // float4 index, 1024 total
                const int ipl = idx >> 5, iv = idx & 31;
                ((float4*)Whs)[ipl * 32 + iv] =
                    ((const float4*)(Wh + (size_t)(h * 128 + ip0 + ipl) * 128))[iv];
            }
            __syncthreads();
            const float* wrow = wksrow + ip0;
#pragma unroll
            for (int ipl = 0; ipl < 32; ipl++) {
                const float w = wrow[ipl];                              // broadcast
                const float4 wh = ((const float4*)Whs)[ipl * 32 + i4];  // conflict-free
                acc.x += w * wh.x; acc.y += w * wh.y;
                acc.z += w * wh.z; acc.w += w * wh.w;
            }
        }
        ((float4*)&g_W2[(size_t)(h * 128 + c0 + cl) * 128])[i4] = acc;
    }
}

// ---------------- smem float layout (all 16B-aligned) ----------------
#define SO_SLAB0 0                         // 15360
#define SO_SLAB1 15360                     // 15360
#define SO_QW    30720                     // 7168 = 14*512 qw[il][h*128+c] (epi partials reuse)
#define SO_ACC   37888                     // 8192 = 512*16 accT[hc][l] stride16 (g1s overlaid)
#define SO_PARTW 46080                     // 1024 = 2*512 wsum partials (2 row-groups)
#define SO_PARTL 47104                     // 2048 = 4*512 logits partials (mask staging overlaid)
#define SO_WT    49152                     // 512   wt[j*4 + h]
#define SO_SW    49664                     // 1696
#define SO_MSK   51360                     // 1696 ints
#define SO_FLAG  53056                     // flags
#define SMEM_FLOATS (SO_FLAG + 8)
#define SMEM_BYTES  (SMEM_FLOATS * 4)      // ~207 KB -> 1 CTA/SM

__device__ __forceinline__ void cpa16(void* dst, const void* src)
{
    unsigned s = (unsigned)__cvta_generic_to_shared(dst);
    asm volatile("cp.async.cg.shared.global [%0], [%1], 16;\n" :: "r"(s), "l"(src));
}
__device__ __forceinline__ void cpa8(void* dst, const void* src)
{
    unsigned s = (unsigned)__cvta_generic_to_shared(dst);
    asm volatile("cp.async.ca.shared.global [%0], [%1], 8;\n" :: "r"(s), "l"(src));
}
__device__ __forceinline__ void cpa_commit()
{
    asm volatile("cp.async.commit_group;\n" ::: "memory");
}

// all-thread slab stage (prologue only)
__device__ __forceinline__ void stage_slab_all(float* dst, const float* gsrc, int tid)
{
#pragma unroll
    for (int w = 0; w < 8; w++) {
        const int idx = tid + w * NTHR;
        if (idx < SLABF / 4) {
            const int j = idx >> 5, q = idx & 31;
            cpa16(dst + j * NI + ((q ^ (j & 7)) << 2), gsrc + idx * 4);
        }
    }
    cpa_commit();
}

// 256-thread slab stage (loop: issued by warps 8-15 only; t in [0,256))
__device__ __forceinline__ void stage_slab_256(float* dst, const float* gsrc, int t)
{
#pragma unroll
    for (int w = 0; w < 15; w++) {
        const int idx = t + w * 256;          // 15*256 == 3840 == SLABF/4 exactly
        const int j = idx >> 5, q = idx & 31;
        cpa16(dst + j * NI + ((q ^ (j & 7)) << 2), gsrc + idx * 4);
    }
    cpa_commit();
}

__global__ __launch_bounds__(NTHR, 1) void attn_pipe(
    const float* __restrict__ g1,
    const float* __restrict__ gg1,
    const void*  __restrict__ maskRaw,
    const float* __restrict__ sw,
    const float* __restrict__ bh,
    float* __restrict__ out,
    int nloctot)
{
    extern __shared__ float sm[];
    float* qw     = sm + SO_QW;
    float* accT   = sm + SO_ACC;
    float* g1s    = accT;                   // prologue overlay [0..1792)
    float* partW  = sm + SO_PARTW;          // [g*512 + h*128 + c], g in {0,1}
    float* partL  = sm + SO_PARTL;          // [kq*512 + h*128 + j]
    int*   mstage = (int*)partL;            // prologue overlay
    float* wt     = sm + SO_WT;
    float* sws    = sm + SO_SW;
    int*   msks   = (int*)(sm + SO_MSK);
    int*   flags  = (int*)(sm + SO_FLAG);

    const int tid = threadIdx.x;
    const int locbase = blockIdx.x * BLOC;
    const int count = min(BLOC, nloctot - locbase);
    if (count <= 0) return;

    if (tid == 0) { flags[0] = 0; flags[1] = 0; }

    // prefetch slabs for loc0 and loc1 (all threads)
    stage_slab_all(sm + SO_SLAB0, gg1 + (size_t)locbase * SLABF, tid);
    stage_slab_all(sm + SO_SLAB1,
                   gg1 + (size_t)(locbase + (count > 1 ? 1 : 0)) * SLABF, tid);

    // mask dtype detection from first 1KB (deterministic)
    if (tid < 64) {
        const uint4 v = ((const uint4*)maskRaw)[tid];
        const unsigned orw = v.x | v.y | v.z | v.w;
        if (orw & 0x00FFFF00u) atomicOr(&flags[0], 1);
        if (orw & 0xFF000000u) atomicOr(&flags[1], 1);
    }
    // g1 rows (overlaid on accT)
    if (tid < 32 * BLOC) {
        const int l = tid >> 5, e4 = tid & 31;
        if (l < count)
            *(float4*)&g1s[l * NI + e4 * 4] =
                *(const float4*)&g1[(size_t)(locbase + l) * NI + e4 * 4];
    }
    __syncthreads();   // B0

    const int f12 = flags[0], f3 = flags[1];
    const int nel = count * NNEI;

    // stage sw + raw mask via cp.async — overlaps qw projection
    {
        const float* swsrc = sw + (size_t)locbase * NNEI;
        for (int t2 = tid; t2 < (nel >> 2); t2 += NTHR)
            cpa16(sws + t2 * 4, swsrc + t2 * 4);
        if (f12) {
            const char* mb = (const char*)maskRaw + (size_t)locbase * NNEI;
            for (int t2 = tid; t2 < (nel >> 3); t2 += NTHR)
                cpa8((char*)mstage + t2 * 8, mb + t2 * 8);
        } else {
            const char* mb = (const char*)maskRaw + (size_t)locbase * NNEI * 4;
            for (int t2 = tid; t2 < (nel >> 2); t2 += NTHR)
                cpa16((char*)mstage + t2 * 16, mb + t2 * 16);
        }
        cpa_commit();
    }

    // qw projection (R7 scalar): qw[l][n] = g1[l,:] . Mq[:,n], n = tid
    {
        float acc[BLOC];
#pragma unroll
        for (int l = 0; l < BLOC; l++) acc[l] = 0.f;
        const float* mq = g_Mq + tid;
#pragma unroll 8
        for (int e = 0; e < NI; e++) {
            const float m = mq[e * HC];
#pragma unroll
            for (int l = 0; l < BLOC; l++)
                acc[l] += g1s[l * NI + e] * m;
        }
        __syncthreads();   // B1: g1s reads done (accT free)
#pragma unroll
        for (int l = 0; l < BLOC; l++) qw[l * HC + tid] = acc[l];
    }

    // drain all prologue groups; convert mask
    asm volatile("cp.async.wait_group 0;\n" ::: "memory");
    __syncthreads();       // B2
#pragma unroll
    for (int w = 0; w < 4; w++) {
        const int t2 = tid + w * NTHR;
        if (t2 < nel) {
            int m;
            if (f12)      m = ((const unsigned char*)mstage)[t2] != 0;
            else if (f3)  m = ((const float*)mstage)[t2] != 0.f;
            else          m = mstage[t2] != 0;
            msks[t2] = m;
        }
    }
    __syncthreads();       // B3: msks ready; partL (mstage) free

    const int wid = tid >> 5, lane = tid & 31;

    // ---- logits(0): full-width R7 mapping ----
    {
        const int kq = wid & 3;
        const int jt = ((wid >> 2) << 5) + lane;
        if (jt < NNEI) {
            const float* gr = sm + SO_SLAB0 + jt * NI + kq * 32;
            const int jm = jt & 7;
            const float4* q0 = (const float4*)(qw + 0 * NI + kq * 32);
            const float4* q1 = (const float4*)(qw + 1 * NI + kq * 32);
            const float4* q2 = (const float4*)(qw + 2 * NI + kq * 32);
            const float4* q3 = (const float4*)(qw + 3 * NI + kq * 32);
            float p0 = 0.f, p1 = 0.f, p2 = 0.f, p3 = 0.f;
#pragma unroll
            for (int i = 0; i < 8; i++) {
                const float4 g = *(const float4*)(gr + ((i ^ jm) << 2));
                const float4 a = q0[i]; p0 += g.x*a.x + g.y*a.y + g.z*a.z + g.w*a.w;
                const float4 b = q1[i]; p1 += g.x*b.x + g.y*b.y + g.z*b.z + g.w*b.w;
                const float4 c = q2[i]; p2 += g.x*c.x + g.y*c.y + g.z*c.z + g.w*c.w;
                const float4 d = q3[i]; p3 += g.x*d.x + g.y*d.y + g.z*d.z + g.w*d.w;
            }
            partL[kq * HC + 0 * NI + jt] = p0;
            partL[kq * HC + 1 * NI + jt] = p1;
            partL[kq * HC + 2 * NI + jt] = p2;
            partL[kq * HC + 3 * NI + jt] = p3;
        }
    }
    __syncthreads();   // B4

    // wsum mapping (warps 0-7): 256 threads, 2 row-groups x 60 rows
    const int cw = tid & 127;
    const int gh = (tid >> 7) & 1;
    const int c4 = cw >> 2, co = cw & 3;
    // logits mapping (warps 8-15): 256 threads, kq quarter + 2 j-rows
    const int tid2 = tid & 255;
    const int wid2 = tid2 >> 5;
    const int kq2 = wid2 & 3;
    const int jb = ((wid2 >> 2) << 5) + lane;   // [0,64)

    // ---------------- per-location pipelined loop ----------------
    for (int il = 0; il < count; il++) {
        // ---- Phase A: softmax(il) on warps 0-3 ; accT(il-1) on warps 4-15 ----
        if (tid < 128) {
            const int h = tid >> 5, ln = tid & 31;
            float lv[4]; int mk[4];
            float mx = -INFINITY;
#pragma unroll
            for (int q = 0; q < 4; q++) {
                const int j = ln + q * 32;
                const int in = (j < NNEI) ? msks[il * NNEI + j] : 0;
                float L = -INFINITY;
                if (in) L = partL[h * NI + j] + partL[HC + h * NI + j]
                          + partL[2 * HC + h * NI + j] + partL[3 * HC + h * NI + j];
                lv[q] = L; mk[q] = in;
                mx = fmaxf(mx, L);
            }
#pragma unroll
            for (int off = 16; off > 0; off >>= 1)
                mx = fmaxf(mx, __shfl_xor_sync(0xFFFFFFFFu, mx, off));
            float ev[4];
            float sum = 0.f;
#pragma unroll
            for (int q = 0; q < 4; q++) {
                ev[q] = mk[q] ? __expf(lv[q] - mx) : 0.f;
                sum += ev[q];
            }
#pragma unroll
            for (int off = 16; off > 0; off >>= 1)
                sum += __shfl_xor_sync(0xFFFFFFFFu, sum, off);
            const float inv = (sum > 0.f) ? (1.f / sum) : 0.f;
#pragma unroll
            for (int q = 0; q < 4; q++) {
                const int j = ln + q * 32;
                if (j < NNEI)
                    wt[j * 4 + h] = mk[q] ? ev[q] * inv * sws[il * NNEI + j] : 0.f;
            }
        } else if (il > 0) {
            for (int v = tid - 128; v < HC; v += 384)
                accT[(v << 4) + il - 1] = partW[v] + partW[HC + v];
        }
        __syncthreads();   // P1

        // ---- Phase B: wsum(il) on warps 0-7 ; wait+logits(il+1) on warps 8-15 ----
        if (tid < 256) {
            float* slab = sm + ((il & 1) ? SO_SLAB1 : SO_SLAB0);
            float s0 = 0.f, s1 = 0.f, s2 = 0.f, s3 = 0.f;
            const int j0 = gh * 60;
#pragma unroll 15
            for (int t = 0; t < 60; t++) {
                const int j = j0 + t;
                const float g = slab[j * NI + (((c4 ^ (j & 7)) << 2) | co)];
                const float4 w = *(const float4*)&wt[j * 4];
                s0 += w.x * g; s1 += w.y * g; s2 += w.z * g; s3 += w.w * g;
            }
            partW[gh * HC + 0 * NI + cw] = s0;
            partW[gh * HC + 1 * NI + cw] = s1;
            partW[gh * HC + 2 * NI + cw] = s2;
            partW[gh * HC + 3 * NI + cw] = s3;
        } else if (il + 1 < count) {
            // Drain OWN cp.async copies, then publish across warps 8-15 via a
            // named partial barrier (all issuers waited before the barrier).
            asm volatile("cp.async.wait_group 0;\n" ::: "memory");
            asm volatile("bar.sync 1, 256;" ::: "memory");
            const float* slab = sm + (((il + 1) & 1) ? SO_SLAB1 : SO_SLAB0);
            const float* qwl = qw + (il + 1) * HC;
            const int jA = jb;
            const int jB = jb + 64;
            const int doB = (jB < NNEI);
            const float* grA = slab + jA * NI + kq2 * 32;
            const float* grB = slab + jB * NI + kq2 * 32;
            const int jmA = jA & 7;
            const int jmB = jB & 7;
            const float4* q0 = (const float4*)(qwl + 0 * NI + kq2 * 32);
            const float4* q1 = (const float4*)(qwl + 1 * NI + kq2 * 32);
            const float4* q2 = (const float4*)(qwl + 2 * NI + kq2 * 32);
            const float4* q3 = (const float4*)(qwl + 3 * NI + kq2 * 32);
            float p0 = 0.f, p1 = 0.f, p2 = 0.f, p3 = 0.f;
            float r0 = 0.f, r1 = 0.f, r2 = 0.f, r3 = 0.f;
#pragma unroll
            for (int i = 0; i < 8; i++) {
                const float4 a = q0[i];
                const float4 b = q1[i];
                const float4 c = q2[i];
                const float4 d = q3[i];
                const float4 gA = *(const float4*)(grA + ((i ^ jmA) << 2));
                p0 += gA.x*a.x + gA.y*a.y + gA.z*a.z + gA.w*a.w;
                p1 += gA.x*b.x + gA.y*b.y + gA.z*b.z + gA.w*b.w;
                p2 += gA.x*c.x + gA.y*c.y + gA.z*c.z + gA.w*c.w;
                p3 += gA.x*d.x + gA.y*d.y + gA.z*d.z + gA.w*d.w;
                if (doB) {
                    const float4 gB = *(const float4*)(grB + ((i ^ jmB) << 2));
                    r0 += gB.x*a.x + gB.y*a.y + gB.z*a.z + gB.w*a.w;
                    r1 += gB.x*b.x + gB.y*b.y + gB.z*b.z + gB.w*b.w;
                    r2 += gB.x*c.x + gB.y*c.y + gB.z*c.z + gB.w*c.w;
                    r3 += gB.x*d.x + gB.y*d.y + gB.z*d.z + gB.w*d.w;
                }
            }
            partL[kq2 * HC + 0 * NI + jA] = p0;
            partL[kq2 * HC + 1 * NI + jA] = p1;
            partL[kq2 * HC + 2 * NI + jA] = p2;
            partL[kq2 * HC + 3 * NI + jA] = p3;
            if (doB) {
                partL[kq2 * HC + 0 * NI + jB] = r0;
                partL[kq2 * HC + 1 * NI + jB] = r1;
                partL[kq2 * HC + 2 * NI + jB] = r2;
                partL[kq2 * HC + 3 * NI + jB] = r3;
            }
        }
        __syncthreads();   // P2: slab il free; partW/partL visible

        // prefetch slab il+2 — issued ONLY by warps 8-15 (they also wait on it)
        if (il + 2 < count && tid >= 256)
            stage_slab_256(sm + ((il & 1) ? SO_SLAB1 : SO_SLAB0),
                           gg1 + (size_t)(locbase + il + 2) * SLABF, tid2);
    }

    // final accT row
    accT[(tid << 4) + (count - 1)] = partW[tid] + partW[HC + tid];
    __syncthreads();

    // ---------------- fused output GEMM (R7 scalar): out[l][128] = a[l][512] @ W2 + bh ----------------
    {
        const int i = tid & 127, h2 = tid >> 7;
        float acc[BLOC];
#pragma unroll
        for (int l = 0; l < BLOC; l++) acc[l] = 0.f;
        const float* w2p = g_W2 + (size_t)(h2 * NI) * NI + i;
#pragma unroll 4
        for (int k = 0; k < 128; k++) {
            const float w2 = w2p[k * NI];
            const float* ap = accT + ((h2 * 128 + k) << 4);
            const float4 v0 = *(const float4*)ap;
            const float4 v1 = *(const float4*)(ap + 4);
            const float4 v2 = *(const float4*)(ap + 8);
            const float2 v3 = *(const float2*)(ap + 12);
            acc[0]  += v0.x * w2; acc[1]  += v0.y * w2;
            acc[2]  += v0.z * w2; acc[3]  += v0.w * w2;
            acc[4]  += v1.x * w2; acc[5]  += v1.y * w2;
            acc[6]  += v1.z * w2; acc[7]  += v1.w * w2;
            acc[8]  += v2.x * w2; acc[9]  += v2.y * w2;
            acc[10] += v2.z * w2; acc[11] += v2.w * w2;
            acc[12] += v3.x * w2; acc[13] += v3.y * w2;
        }
        __syncthreads();
#pragma unroll
        for (int l = 0; l < BLOC; l++)
            qw[h2 * (BLOC * NI) + l * NI + i] = acc[l];   // reuse qw as partials
    }
    __syncthreads();
    for (int o = tid; o < BLOC * NI; o += NTHR) {
        const int l = o >> 7, ii = o & 127;
        if (l < count) {
            const float v = qw[o] + qw[BLOC * NI + o]
                          + qw[2 * BLOC * NI + o] + qw[3 * BLOC * NI + o] + bh[ii];
            out[(size_t)(locbase + l) * NI + ii] = v;
        }
    }
}

// ---------------- launch ----------------
extern "C" void kernel_launch(void* const* d_in, const int* in_sizes, int n_in,
                              void* d_out, int out_size)
{
    const float* g1   = (const float*)d_in[0];
    const float* gg1  = (const float*)d_in[1];
    const void*  mask = d_in[2];
    const float* sw   = (const float*)d_in[3];
    const float* Wq   = (const float*)d_in[4];
    const float* Wkv  = (const float*)d_in[5];
    const float* Wh   = (const float*)d_in[6];
    const float* bh   = (const float*)d_in[7];
    float* out = (float*)d_out;

    const int nloctot = in_sizes[0] / NI;   // 2048

    static int smem_cfg = 0;
    if (!smem_cfg) {
        cudaFuncSetAttribute(attn_pipe, cudaFuncAttributeMaxDynamicSharedMemorySize, SMEM_BYTES);
        smem_cfg = 1;
    }

    const int grid = (nloctot + BLOC - 1) / BLOC;   // 147

    wprep_tiled<<<80, 256>>>(Wq, Wkv, Wh);
    attn_pipe<<<grid, NTHR, SMEM_BYTES>>>(g1, gg1, mask, sw, bh, out, nloctot);
}